// round 6
// baseline (speedup 1.0000x reference)
#include <cuda_runtime.h>
#include <cuda.h>
#include <cuda_fp16.h>
#include <cstdint>

// ---- arch gating: tcgen05 / cta_group::2 / TMA-multicast are only legal on
// arch-specific targets; the harness also builds a plain compute_103 PTX pass
// where ptxas rejects them.
#if !defined(__CUDA_ARCH__) || defined(__CUDA_ARCH_FEAT_SM103_ALL) || \
    defined(__CUDA_ARCH_FEAT_SM100_ALL) || defined(__CUDA_ARCH_FEAT_SM101_ALL) || \
    (defined(__CUDA_ARCH_FAMILY_SPECIFIC__) && (__CUDA_ARCH_FAMILY_SPECIFIC__ >= 1000))
#define GB300_TCGEN05 1
#else
#define GB300_TCGEN05 0
#endif

// ======================= problem constants =======================
static constexpr int MM = 8192;
static constexpr int KK = 4096;
static constexpr int NN = 16384;
static constexpr int SCALE_KB = KK / 128;

// ======================= gemm tiling =======================
// 4-CTA cluster = 2 cg2 pairs sharing one 512-N range (B multicast {0,2},{1,3}).
// Cluster tile: 512M x 512N. PERSISTENT: 32 clusters x 16 tiles each.
static constexpr int BK         = 64;
static constexpr int STAGES     = 4;
static constexpr int KCHUNKS    = KK / BK;          // 64
static constexpr int TILES_N    = NN / 512;         // 32
static constexpr int TILES_TOT  = (MM / 512) * TILES_N;  // 512 cluster tiles
static constexpr int NCLUST     = 32;               // resident clusters
static constexpr int GRID       = NCLUST * 4;       // 128 CTAs
static constexpr int NROUNDS    = TILES_TOT / NCLUST;    // 16 tiles per cluster
static constexpr int GROUP_M    = 8;

// smem layout
static constexpr int SM_TMEM_PTR   = 0;
static constexpr int SM_FULLA      = 16;    // 4 x 8B
static constexpr int SM_FULLB      = 48;    // 4 x 8B
static constexpr int SM_EMPTY      = 80;    // 4 x 8B
static constexpr int SM_DONE       = 112;   // 8B
static constexpr int SM_ACCFREE    = 120;   // 2 x 8B (per 256-col half)
static constexpr int A_STAGE_BYTES = 128 * 128;
static constexpr int B_STAGE_BYTES = 2 * 128 * 128;
static constexpr int SM_A          = 1024;
static constexpr int SM_B          = SM_A + STAGES * A_STAGE_BYTES;
static constexpr int SMEM_TOTAL    = SM_B + STAGES * B_STAGE_BYTES;   // 197632
static constexpr unsigned A_TX     = 2u * 128u * 128u;
static constexpr unsigned B_TX     = 2u * 128u * 128u;

// idesc kind::f16, f16 in, fp32 acc, M=256 (cg2), N=256
static constexpr uint32_t IDESC_F16 =
    (1u << 4) | ((256u / 8) << 17) | ((256u / 16) << 24);

static constexpr uint64_t SMEM_DESC_BASE_SW128 =
    (uint64_t(2) << 61) | (uint64_t(1) << 46) | (uint64_t(64) << 32) | (uint64_t(1) << 16);
#define MAKE_SMEM_DESC(base_addr) (SMEM_DESC_BASE_SW128 | ((uint64_t)((base_addr) >> 4) & 0x3FFF))

// ======================= device scratch =======================
__device__ __align__(1024) __half g_x_h[(size_t)MM * KK];   // 64 MB
__device__ __align__(1024) __half g_w_h[(size_t)NN * KK];   // 128 MB

// ======================= PTX helpers =======================
__device__ __forceinline__ uint32_t smem_u32(const void* p) {
    uint32_t a;
    asm("{ .reg .u64 t; cvta.to.shared.u64 t, %1; cvt.u32.u64 %0, t; }" : "=r"(a) : "l"(p));
    return a;
}
__device__ __forceinline__ uint32_t ctarank() {
    uint32_t r; asm("mov.u32 %0, %%cluster_ctarank;" : "=r"(r)); return r;
}

#define MBAR_INIT(addr, cnt) \
    asm volatile("mbarrier.init.shared.b64 [%0], %1;" :: "r"(addr), "r"(cnt) : "memory")
#define MBAR_INVAL(addr) \
    asm volatile("mbarrier.inval.shared.b64 [%0];" :: "r"(addr) : "memory")
#define MBAR_EXPECT_TX(addr, bytes) \
    asm volatile("mbarrier.arrive.expect_tx.shared.b64 _, [%0], %1;" :: "r"(addr), "r"(bytes) : "memory")

#define MBAR_WAIT(addr, parity) do {                                                    \
    uint32_t _m = (uint32_t)(addr); uint32_t _p = (uint32_t)(parity); uint32_t _d;      \
    asm volatile("{\n\t.reg .pred p;\n\t"                                               \
        "mbarrier.try_wait.parity.acquire.cta.shared::cta.b64 p, [%1], %2;\n\t"         \
        "selp.b32 %0, 1, 0, p;\n\t}" : "=r"(_d) : "r"(_m), "r"(_p) : "memory");         \
    if (!_d) {                                                                          \
        asm volatile("{\n\t.reg .pred P1;\n\t"                                          \
            "WAIT_LOOP_%=:\n\t"                                                         \
            "mbarrier.try_wait.parity.acquire.cta.shared::cta.b64 P1, [%0], %1, 0x989680;\n\t" \
            "@P1 bra.uni WAIT_DONE_%=;\n\t"                                             \
            "bra.uni WAIT_LOOP_%=;\n\t"                                                 \
            "WAIT_DONE_%=:\n\t}" :: "r"(_m), "r"(_p) : "memory");                       \
    }                                                                                   \
} while (0)

#define MBAR_WAIT_RELAXED(addr, parity) do {                                            \
    uint32_t _m = (uint32_t)(addr); uint32_t _p = (uint32_t)(parity); uint32_t _d;      \
    asm volatile("{\n\t.reg .pred p;\n\t"                                               \
        "mbarrier.try_wait.parity.relaxed.cta.shared::cta.b64 p, [%1], %2, 0x989680;\n\t" \
        "selp.b32 %0, 1, 0, p;\n\t}" : "=r"(_d) : "r"(_m), "r"(_p) : "memory");         \
    if (!_d) {                                                                          \
        asm volatile("{\n\t.reg .pred P1;\n\t"                                          \
            "WAIT_LOOP_%=:\n\t"                                                         \
            "mbarrier.try_wait.parity.relaxed.cta.shared::cta.b64 P1, [%0], %1, 0x989680;\n\t" \
            "@P1 bra.uni WAIT_DONE_%=;\n\t"                                             \
            "bra.uni WAIT_LOOP_%=;\n\t"                                                 \
            "WAIT_DONE_%=:\n\t}" :: "r"(_m), "r"(_p) : "memory");                       \
    }                                                                                   \
} while (0)

#if GB300_TCGEN05
#define TMA_LOAD_3D_CG2(smem_addr, map_ptr, cx, cy, cz, mbar) \
    asm volatile("{\n\t.reg .b32 lb;\n\t"                                               \
        "and.b32 lb, %5, 0xFEFFFFFF;\n\t"                                               \
        "cp.async.bulk.tensor.3d.cta_group::2.shared::cluster.global"                   \
        ".tile.mbarrier::complete_tx::bytes [%0], [%1, {%2, %3, %4}], [lb];\n\t}"       \
        :: "r"((uint32_t)(smem_addr)), "l"(map_ptr),                                    \
           "r"((int32_t)(cx)), "r"((int32_t)(cy)), "r"((int32_t)(cz)),                  \
           "r"((uint32_t)(mbar)) : "memory")

#define TMA_LOAD_3D_MC(smem_addr, map_ptr, cx, cy, cz, mbar, cta_mask) \
    asm volatile("cp.async.bulk.tensor.3d.shared::cluster.global"                       \
        ".tile.mbarrier::complete_tx::bytes.multicast::cluster "                        \
        "[%0], [%1, {%2, %3, %4}], [%5], %6;"                                           \
        :: "r"((uint32_t)(smem_addr)), "l"(map_ptr),                                    \
           "r"((int32_t)(cx)), "r"((int32_t)(cy)), "r"((int32_t)(cz)),                  \
           "r"((uint32_t)(mbar)), "h"((uint16_t)(cta_mask)) : "memory")

#define MBAR_ARRIVE_REMOTE(local_addr, target_rank) \
    asm volatile("{\n\t.reg .b32 ra;\n\t"                                               \
        "mapa.shared::cluster.u32 ra, %0, %1;\n\t"                                      \
        "mbarrier.arrive.shared::cluster.b64 _, [ra];\n\t}"                             \
        :: "r"((uint32_t)(local_addr)), "r"((uint32_t)(target_rank)) : "memory")

#define TCGEN05_ALLOC_CG2(smem_res, ncols) \
    asm volatile("tcgen05.alloc.cta_group::2.sync.aligned.shared::cta.b32 [%0], %1;"    \
        :: "r"((uint32_t)(smem_res)), "r"((uint32_t)(ncols)) : "memory")
#define TCGEN05_DEALLOC_CG2(tmem, ncols) \
    asm volatile("tcgen05.dealloc.cta_group::2.sync.aligned.b32 %0, %1;" :: "r"(tmem), "r"(ncols))
#define TCGEN05_RELINQ_CG2() \
    asm volatile("tcgen05.relinquish_alloc_permit.cta_group::2.sync.aligned;")
#define TCGEN05_COMMIT_MC_CG2(mbar, mask) \
    asm volatile("tcgen05.commit.cta_group::2.mbarrier::arrive::one.shared::cluster.multicast::cluster.b64 [%0], %1;" \
        :: "r"((uint32_t)(mbar)), "h"((uint16_t)(mask)) : "memory")
#define TCGEN05_FENCE_BEFORE() asm volatile("tcgen05.fence::before_thread_sync;" ::: "memory")
#define TCGEN05_FENCE_AFTER()  asm volatile("tcgen05.fence::after_thread_sync;" ::: "memory")
#define TCGEN05_WAIT_LD()      asm volatile("tcgen05.wait::ld.sync.aligned;" ::: "memory")

#define TCGEN05_LD_32X32B_X32(r, tmem_addr) \
    asm volatile("tcgen05.ld.sync.aligned.32x32b.x32.b32 "                              \
        "{%0, %1, %2, %3, %4, %5, %6, %7, "                                             \
        " %8, %9, %10, %11, %12, %13, %14, %15, "                                       \
        " %16, %17, %18, %19, %20, %21, %22, %23, "                                     \
        " %24, %25, %26, %27, %28, %29, %30, %31}, [%32];"                              \
        : "=r"((r)[0]),  "=r"((r)[1]),  "=r"((r)[2]),  "=r"((r)[3]),                    \
          "=r"((r)[4]),  "=r"((r)[5]),  "=r"((r)[6]),  "=r"((r)[7]),                    \
          "=r"((r)[8]),  "=r"((r)[9]),  "=r"((r)[10]), "=r"((r)[11]),                   \
          "=r"((r)[12]), "=r"((r)[13]), "=r"((r)[14]), "=r"((r)[15]),                   \
          "=r"((r)[16]), "=r"((r)[17]), "=r"((r)[18]), "=r"((r)[19]),                   \
          "=r"((r)[20]), "=r"((r)[21]), "=r"((r)[22]), "=r"((r)[23]),                   \
          "=r"((r)[24]), "=r"((r)[25]), "=r"((r)[26]), "=r"((r)[27]),                   \
          "=r"((r)[28]), "=r"((r)[29]), "=r"((r)[30]), "=r"((r)[31])                    \
        : "r"(tmem_addr))
#endif // GB300_TCGEN05

#define CLUSTER_SYNC() do {                                                             \
    asm volatile("barrier.cluster.arrive.aligned;" ::: "memory");                       \
    asm volatile("barrier.cluster.wait.aligned;" ::: "memory");                         \
} while (0)

__device__ __forceinline__ void mma_f16_ss_cg2(
    uint32_t d_tmem, uint64_t a_desc, uint64_t b_desc, uint32_t idesc, bool enable_d)
{
#if GB300_TCGEN05
    uint32_t en = enable_d ? 1u : 0u;
    asm volatile(
        "{\n\t.reg .pred p;\n\t"
        "setp.ne.u32 p, %5, 0;\n\t"
        "tcgen05.mma.cta_group::2.kind::f16 [%0], %1, %2, %3, "
        "{%4, %4, %4, %4, %4, %4, %4, %4}, p;\n\t}"
        :: "r"(d_tmem), "l"(a_desc), "l"(b_desc), "r"(idesc), "r"(0u), "r"(en)
        : "memory");
#endif
}

// tileid -> (m_base512, n_base) with GROUP_M supertile swizzle
__device__ __forceinline__ void tile_coords(int tileid, int& m512, int& nb) {
    const int group  = tileid / (GROUP_M * TILES_N);
    const int within = tileid % (GROUP_M * TILES_N);
    m512 = group * GROUP_M + (within % GROUP_M);
    nb   = within / GROUP_M;
}

// ======================= kernel 1: fused prep =======================
static constexpr int XB = (MM * KK / 4) / 256;   // 32768
static constexpr int WB = (NN * KK / 4) / 256;   // 65536

__global__ void __launch_bounds__(256) prep_kernel(
    const float* __restrict__ x, const float* __restrict__ w,
    const float* __restrict__ sc,
    __half* __restrict__ xh, __half* __restrict__ wh)
{
    int b = blockIdx.x;
    if (b < XB) {
        int i = b * 256 + threadIdx.x;
        float4 v = reinterpret_cast<const float4*>(x)[i];
        union { __half2 h[2]; uint2 u; } cv;
        cv.h[0] = __floats2half2_rn(v.x, v.y);
        cv.h[1] = __floats2half2_rn(v.z, v.w);
        reinterpret_cast<uint2*>(xh)[i] = cv.u;
    } else {
        int i = (b - XB) * 256 + threadIdx.x;
        int n  = i >> 10;
        int k4 = i & 1023;
        float s = __ldg(&sc[(n >> 7) * SCALE_KB + (k4 >> 5)]);
        float4 v = reinterpret_cast<const float4*>(w)[i];
        union { __half2 h[2]; uint2 u; } cv;
        cv.h[0] = __floats2half2_rn(v.x * s, v.y * s);
        cv.h[1] = __floats2half2_rn(v.z * s, v.w * s);
        reinterpret_cast<uint2*>(wh)[i] = cv.u;
    }
}

// ======================= kernel 2: PERSISTENT cluster-4 GEMM =======================
__global__ void __launch_bounds__(192, 1)
gemm_f16_kernel(const __grid_constant__ CUtensorMap tma_a,
                const __grid_constant__ CUtensorMap tma_b,
                const float* __restrict__ bias,
                float* __restrict__ out)
{
#if GB300_TCGEN05
    extern __shared__ char smem[];
    const uint32_t sb   = smem_u32(smem);
    const int tid       = threadIdx.x;
    const int wid       = tid >> 5;
    const int lid       = tid & 31;
    const uint32_t rank = ctarank();          // 0..3
    const int P   = (int)(rank >> 1);
    const int rp  = (int)(rank & 1);
    const int cid = blockIdx.x >> 2;          // cluster id [0, 32)
    const uint32_t pair_leader = rank & ~1u;

    // ---- init ----
    if (tid == 0) {
        #pragma unroll
        for (int s = 0; s < STAGES; s++) {
            MBAR_INIT(sb + SM_FULLA + s * 8, 1);
            MBAR_INIT(sb + SM_FULLB + s * 8, rp ? 1 : 2);   // leader: own tx + follower fwd
            MBAR_INIT(sb + SM_EMPTY + s * 8, 2);            // both pair-leader commits
        }
        MBAR_INIT(sb + SM_DONE, 1);
        MBAR_INIT(sb + SM_ACCFREE + 0, 8);   // 4 warps x 2 CTAs arrive per tile
        MBAR_INIT(sb + SM_ACCFREE + 8, 8);
    }
    if (wid == 5) TCGEN05_ALLOC_CG2(sb + SM_TMEM_PTR, 512);
    __syncthreads();
    uint32_t tmem_base;
    asm volatile("ld.shared.b32 %0, [%1];" : "=r"(tmem_base) : "r"(sb + SM_TMEM_PTR));
    CLUSTER_SYNC();

    // ---- producer: one thread per CTA, flat loop over all (tile, kc) ----
    if (tid == 128) {
        const uint16_t bmask = rank == 0 ? 0x5 : 0xA;   // {0,2} or {1,3}
        for (int j = 0; j < NROUNDS * KCHUNKS; ++j) {
            const int tile = j >> 6;
            const int kc   = j & (KCHUNKS - 1);
            int m512, nb;
            tile_coords(tile * NCLUST + cid, m512, nb);
            const int m_base_cta = m512 * 512 + P * 256 + rp * 128;
            const int n_base     = nb * 512;

            const int s = j & (STAGES - 1);
            const int r = j >> 2;
            if (r > 0) MBAR_WAIT_RELAXED(sb + SM_EMPTY + s * 8, (r - 1) & 1);
            const int kco = kc * BK;
            if (rp == 0) MBAR_EXPECT_TX(sb + SM_FULLA + s * 8, A_TX);
            TMA_LOAD_3D_CG2(sb + SM_A + s * A_STAGE_BYTES, &tma_a,
                            kco, m_base_cta, 0, sb + SM_FULLA + s * 8);
            MBAR_EXPECT_TX(sb + SM_FULLB + s * 8, B_TX);
            if (rank < 2) {
                TMA_LOAD_3D_MC(sb + SM_B + s * B_STAGE_BYTES, &tma_b,
                               kco, n_base + rp * 128, 0,
                               sb + SM_FULLB + s * 8, bmask);
                TMA_LOAD_3D_MC(sb + SM_B + s * B_STAGE_BYTES + 16384, &tma_b,
                               kco, n_base + 256 + rp * 128, 0,
                               sb + SM_FULLB + s * 8, bmask);
            }
        }
    }

    // ---- tid 160: MMA issuer (even ranks) / B-forwarder (odd ranks) ----
    if (tid == 160) {
        if (rp == 0) {
            for (int tile = 0; tile < NROUNDS; ++tile) {
                // accumulator half 0 must be drained by previous tile's epilogue
                if (tile > 0) { MBAR_WAIT(sb + SM_ACCFREE + 0, (tile - 1) & 1); TCGEN05_FENCE_AFTER(); }
                for (int kc = 0; kc < KCHUNKS; ++kc) {
                    const int j = tile * KCHUNKS + kc;
                    const int s = j & (STAGES - 1);
                    const int r = j >> 2;
                    MBAR_WAIT(sb + SM_FULLA + s * 8, r & 1);
                    MBAR_WAIT(sb + SM_FULLB + s * 8, r & 1);
                    const uint64_t ad = MAKE_SMEM_DESC(sb + SM_A + s * A_STAGE_BYTES);
                    const uint64_t bd0 = MAKE_SMEM_DESC(sb + SM_B + s * B_STAGE_BYTES);
                    #pragma unroll
                    for (int ks = 0; ks < 4; ++ks)
                        mma_f16_ss_cg2(tmem_base, ad + ks * 2, bd0 + ks * 2,
                                       IDESC_F16, kc > 0 || ks > 0);
                    if (kc == 0 && tile > 0) { MBAR_WAIT(sb + SM_ACCFREE + 8, (tile - 1) & 1); TCGEN05_FENCE_AFTER(); }
                    const uint64_t bd1 = MAKE_SMEM_DESC(sb + SM_B + s * B_STAGE_BYTES + 16384);
                    #pragma unroll
                    for (int ks = 0; ks < 4; ++ks)
                        mma_f16_ss_cg2(tmem_base + 256, ad + ks * 2, bd1 + ks * 2,
                                       IDESC_F16, kc > 0 || ks > 0);
                    TCGEN05_COMMIT_MC_CG2(sb + SM_EMPTY + s * 8, 0xF);
                }
                TCGEN05_COMMIT_MC_CG2(sb + SM_DONE, rank == 0 ? 0x3 : 0xC);
            }
        } else {
            // follower: forward own B arrival to pair leader's fullB
            for (int j = 0; j < NROUNDS * KCHUNKS; ++j) {
                const int s = j & (STAGES - 1);
                const int r = j >> 2;
                MBAR_WAIT(sb + SM_FULLB + s * 8, r & 1);
                MBAR_ARRIVE_REMOTE(sb + SM_FULLB + s * 8, pair_leader);
            }
        }
    }

    // ---- epilogue: warps 0-3 on all CTAs ----
    if (wid < 4) {
        for (int tile = 0; tile < NROUNDS; ++tile) {
            MBAR_WAIT(sb + SM_DONE, tile & 1);
            TCGEN05_FENCE_AFTER();
            int m512, nb;
            tile_coords(tile * NCLUST + cid, m512, nb);
            const int m = m512 * 512 + P * 256 + rp * 128 + wid * 32 + lid;
            const int n_base = nb * 512;
            float* orow = out + (size_t)m * NN + n_base;
            #pragma unroll 1
            for (int cc = 0; cc < 16; ++cc) {
                uint32_t r[32];
                TCGEN05_LD_32X32B_X32(r, tmem_base + cc * 32);
                TCGEN05_WAIT_LD();
                if (cc == 7 || cc == 15) {    // half fully read -> release to next MMA
                    TCGEN05_FENCE_BEFORE();
                    if (lid == 0) MBAR_ARRIVE_REMOTE(sb + SM_ACCFREE + (cc == 7 ? 0 : 8), pair_leader);
                }
                const int n0 = cc * 32;
                #pragma unroll
                for (int q = 0; q < 8; ++q) {
                    float4 bv = __ldg(reinterpret_cast<const float4*>(bias + n_base + n0 + q * 4));
                    float4 o;
                    o.x = __uint_as_float(r[q * 4 + 0]) + bv.x;
                    o.y = __uint_as_float(r[q * 4 + 1]) + bv.y;
                    o.z = __uint_as_float(r[q * 4 + 2]) + bv.z;
                    o.w = __uint_as_float(r[q * 4 + 3]) + bv.w;
                    reinterpret_cast<float4*>(orow + n0)[q] = o;
                }
            }
        }
    }

    // ---- teardown ----
    __syncthreads();
    if (tid == 0) {
        #pragma unroll
        for (int s = 0; s < STAGES; s++) {
            MBAR_INVAL(sb + SM_FULLA + s * 8);
            MBAR_INVAL(sb + SM_FULLB + s * 8);
            MBAR_INVAL(sb + SM_EMPTY + s * 8);
        }
        MBAR_INVAL(sb + SM_DONE);
        MBAR_INVAL(sb + SM_ACCFREE + 0);
        MBAR_INVAL(sb + SM_ACCFREE + 8);
    }
    __syncthreads();
    CLUSTER_SYNC();
    if (wid == 5) {
        TCGEN05_RELINQ_CG2();
        TCGEN05_DEALLOC_CG2(tmem_base, 512);
    }
    CLUSTER_SYNC();
#endif // GB300_TCGEN05
}

// ======================= host =======================
typedef CUresult (*PFN_tmapEncode)(
    CUtensorMap*, CUtensorMapDataType, cuuint32_t, void*,
    const cuuint64_t*, const cuuint64_t*, const cuuint32_t*, const cuuint32_t*,
    CUtensorMapInterleave, CUtensorMapSwizzle, CUtensorMapL2promotion, CUtensorMapFloatOOBfill);

static void make_kmajor_map(PFN_tmapEncode enc, CUtensorMap* m, void* base,
                            cuuint64_t d0, cuuint64_t d1)
{
    cuuint64_t dims[3]    = {d0, d1, 1};
    cuuint64_t strides[2] = {d0 * 2, d0 * d1 * 2};
    cuuint32_t box[3]     = {64, 128, 1};
    cuuint32_t es[3]      = {1, 1, 1};
    enc(m, CU_TENSOR_MAP_DATA_TYPE_FLOAT16, 3, base, dims, strides, box, es,
        CU_TENSOR_MAP_INTERLEAVE_NONE, CU_TENSOR_MAP_SWIZZLE_128B,
        CU_TENSOR_MAP_L2_PROMOTION_L2_128B, CU_TENSOR_MAP_FLOAT_OOB_FILL_NONE);
}

extern "C" void kernel_launch(void* const* d_in, const int* in_sizes, int n_in,
                              void* d_out, int out_size)
{
    const float* x    = (const float*)d_in[0];
    const float* w    = (const float*)d_in[1];
    const float* sc   = (const float*)d_in[2];
    const float* bias = (const float*)d_in[3];
    float* out        = (float*)d_out;

    void *xh = nullptr, *wh = nullptr;
    cudaGetSymbolAddress(&xh, g_x_h);
    cudaGetSymbolAddress(&wh, g_w_h);

    prep_kernel<<<XB + WB, 256>>>(x, w, sc, (__half*)xh, (__half*)wh);

    PFN_tmapEncode enc = nullptr;
    cudaDriverEntryPointQueryResult qr;
    cudaGetDriverEntryPoint("cuTensorMapEncodeTiled", (void**)&enc, cudaEnableDefault, &qr);
    if (!enc) return;

    CUtensorMap ta, tb;
    make_kmajor_map(enc, &ta, xh, (cuuint64_t)KK, (cuuint64_t)MM);
    make_kmajor_map(enc, &tb, wh, (cuuint64_t)KK, (cuuint64_t)NN);

    cudaFuncSetAttribute(gemm_f16_kernel,
                         cudaFuncAttributeMaxDynamicSharedMemorySize, SMEM_TOTAL);

    cudaLaunchConfig_t cfg = {};
    cfg.gridDim          = dim3(GRID, 1, 1);
    cfg.blockDim         = dim3(192, 1, 1);
    cfg.dynamicSmemBytes = SMEM_TOTAL;
    cfg.stream           = 0;
    cudaLaunchAttribute at[1];
    at[0].id = cudaLaunchAttributeClusterDimension;
    at[0].val.clusterDim.x = 4;
    at[0].val.clusterDim.y = 1;
    at[0].val.clusterDim.z = 1;
    cfg.attrs    = at;
    cfg.numAttrs = 1;
    cudaLaunchKernelEx(&cfg, gemm_f16_kernel, ta, tb, bias, out);
}

// round 7
// speedup vs baseline: 1.0140x; 1.0140x over previous
#include <cuda_runtime.h>
#include <cuda.h>
#include <cuda_fp16.h>
#include <cstdint>

// ---- arch gating: tcgen05 / cta_group::2 / TMA-multicast are only legal on
// arch-specific targets; the harness also builds a plain compute_103 PTX pass
// where ptxas rejects them.
#if !defined(__CUDA_ARCH__) || defined(__CUDA_ARCH_FEAT_SM103_ALL) || \
    defined(__CUDA_ARCH_FEAT_SM100_ALL) || defined(__CUDA_ARCH_FEAT_SM101_ALL) || \
    (defined(__CUDA_ARCH_FAMILY_SPECIFIC__) && (__CUDA_ARCH_FAMILY_SPECIFIC__ >= 1000))
#define GB300_TCGEN05 1
#else
#define GB300_TCGEN05 0
#endif

// ======================= problem constants =======================
static constexpr int MM = 8192;
static constexpr int KK = 4096;
static constexpr int NN = 16384;
static constexpr int SCALE_KB = KK / 128;

// ======================= gemm tiling =======================
// 4-CTA cluster = 2 cg2 pairs sharing one 512-N range (B multicast {0,2},{1,3}).
// Cluster tile: 512M x 512N. PERSISTENT: 32 clusters x 16 tiles each.
// B loads use cta_group::2 + multicast: each receiver's complete_tx lands on its
// PAIR-LEADER's barrier, so follower B arrival needs no software forwarding.
static constexpr int BK         = 64;
static constexpr int STAGES     = 4;
static constexpr int KCHUNKS    = KK / BK;          // 64
static constexpr int TILES_N    = NN / 512;         // 32
static constexpr int TILES_TOT  = (MM / 512) * TILES_N;  // 512
static constexpr int NCLUST     = 32;
static constexpr int GRID       = NCLUST * 4;       // 128 CTAs
static constexpr int NROUNDS    = TILES_TOT / NCLUST;    // 16
static constexpr int GROUP_M    = 8;

// smem layout
static constexpr int SM_TMEM_PTR   = 0;
static constexpr int SM_FULL       = 16;    // 4 x 8B (merged A+B, pair-leader only)
static constexpr int SM_EMPTY      = 48;    // 4 x 8B
static constexpr int SM_DONE       = 80;    // 8B
static constexpr int SM_ACCFREE    = 88;    // 2 x 8B (per 256-col half)
static constexpr int A_STAGE_BYTES = 128 * 128;          // 16 KB per CTA
static constexpr int B_STAGE_BYTES = 2 * 128 * 128;      // 32 KB per CTA
static constexpr int SM_A          = 1024;
static constexpr int SM_B          = SM_A + STAGES * A_STAGE_BYTES;
static constexpr int SMEM_TOTAL    = SM_B + STAGES * B_STAGE_BYTES;   // 197632
// pair totals per stage: A 2x16K + B 4 halves x 16K = 98304
static constexpr unsigned FULL_TX  = 6u * 128u * 128u;

// idesc kind::f16, f16 in, fp32 acc, M=256 (cg2), N=256
static constexpr uint32_t IDESC_F16 =
    (1u << 4) | ((256u / 8) << 17) | ((256u / 16) << 24);

static constexpr uint64_t SMEM_DESC_BASE_SW128 =
    (uint64_t(2) << 61) | (uint64_t(1) << 46) | (uint64_t(64) << 32) | (uint64_t(1) << 16);
#define MAKE_SMEM_DESC(base_addr) (SMEM_DESC_BASE_SW128 | ((uint64_t)((base_addr) >> 4) & 0x3FFF))

// ======================= device scratch =======================
__device__ __align__(1024) __half g_x_h[(size_t)MM * KK];   // 64 MB
__device__ __align__(1024) __half g_w_h[(size_t)NN * KK];   // 128 MB

// ======================= PTX helpers =======================
__device__ __forceinline__ uint32_t smem_u32(const void* p) {
    uint32_t a;
    asm("{ .reg .u64 t; cvta.to.shared.u64 t, %1; cvt.u32.u64 %0, t; }" : "=r"(a) : "l"(p));
    return a;
}
__device__ __forceinline__ uint32_t ctarank() {
    uint32_t r; asm("mov.u32 %0, %%cluster_ctarank;" : "=r"(r)); return r;
}

#define MBAR_INIT(addr, cnt) \
    asm volatile("mbarrier.init.shared.b64 [%0], %1;" :: "r"(addr), "r"(cnt) : "memory")
#define MBAR_INVAL(addr) \
    asm volatile("mbarrier.inval.shared.b64 [%0];" :: "r"(addr) : "memory")
#define MBAR_EXPECT_TX(addr, bytes) \
    asm volatile("mbarrier.arrive.expect_tx.shared.b64 _, [%0], %1;" :: "r"(addr), "r"(bytes) : "memory")

#define MBAR_WAIT(addr, parity) do {                                                    \
    uint32_t _m = (uint32_t)(addr); uint32_t _p = (uint32_t)(parity); uint32_t _d;      \
    asm volatile("{\n\t.reg .pred p;\n\t"                                               \
        "mbarrier.try_wait.parity.acquire.cta.shared::cta.b64 p, [%1], %2;\n\t"         \
        "selp.b32 %0, 1, 0, p;\n\t}" : "=r"(_d) : "r"(_m), "r"(_p) : "memory");         \
    if (!_d) {                                                                          \
        asm volatile("{\n\t.reg .pred P1;\n\t"                                          \
            "WAIT_LOOP_%=:\n\t"                                                         \
            "mbarrier.try_wait.parity.acquire.cta.shared::cta.b64 P1, [%0], %1, 0x989680;\n\t" \
            "@P1 bra.uni WAIT_DONE_%=;\n\t"                                             \
            "bra.uni WAIT_LOOP_%=;\n\t"                                                 \
            "WAIT_DONE_%=:\n\t}" :: "r"(_m), "r"(_p) : "memory");                       \
    }                                                                                   \
} while (0)

#define MBAR_WAIT_RELAXED(addr, parity) do {                                            \
    uint32_t _m = (uint32_t)(addr); uint32_t _p = (uint32_t)(parity); uint32_t _d;      \
    asm volatile("{\n\t.reg .pred p;\n\t"                                               \
        "mbarrier.try_wait.parity.relaxed.cta.shared::cta.b64 p, [%1], %2, 0x989680;\n\t" \
        "selp.b32 %0, 1, 0, p;\n\t}" : "=r"(_d) : "r"(_m), "r"(_p) : "memory");         \
    if (!_d) {                                                                          \
        asm volatile("{\n\t.reg .pred P1;\n\t"                                          \
            "WAIT_LOOP_%=:\n\t"                                                         \
            "mbarrier.try_wait.parity.relaxed.cta.shared::cta.b64 P1, [%0], %1, 0x989680;\n\t" \
            "@P1 bra.uni WAIT_DONE_%=;\n\t"                                             \
            "bra.uni WAIT_LOOP_%=;\n\t"                                                 \
            "WAIT_DONE_%=:\n\t}" :: "r"(_m), "r"(_p) : "memory");                       \
    }                                                                                   \
} while (0)

#if GB300_TCGEN05
// cg2 TMA load (no multicast): issuing CTA loads its own box; complete_tx
// targets the pair-leader's barrier (bit 24 cleared).
#define TMA_LOAD_3D_CG2(smem_addr, map_ptr, cx, cy, cz, mbar) \
    asm volatile("{\n\t.reg .b32 lb;\n\t"                                               \
        "and.b32 lb, %5, 0xFEFFFFFF;\n\t"                                               \
        "cp.async.bulk.tensor.3d.cta_group::2.shared::cluster.global"                   \
        ".tile.mbarrier::complete_tx::bytes [%0], [%1, {%2, %3, %4}], [lb];\n\t}"       \
        :: "r"((uint32_t)(smem_addr)), "l"(map_ptr),                                    \
           "r"((int32_t)(cx)), "r"((int32_t)(cy)), "r"((int32_t)(cz)),                  \
           "r"((uint32_t)(mbar)) : "memory")

// cg2 + multicast TMA load: data delivered to every CTA in cta_mask at the same
// SMEM offset; each receiver's complete_tx is credited to its PAIR-LEADER's
// barrier at the same offset (SM100_TMA_2SM_LOAD_MULTICAST pattern).
#define TMA_LOAD_3D_CG2_MC(smem_addr, map_ptr, cx, cy, cz, mbar, cta_mask) \
    asm volatile("{\n\t.reg .b32 lb;\n\t"                                               \
        "and.b32 lb, %5, 0xFEFFFFFF;\n\t"                                               \
        "cp.async.bulk.tensor.3d.cta_group::2.shared::cluster.global"                   \
        ".tile.mbarrier::complete_tx::bytes.multicast::cluster "                        \
        "[%0], [%1, {%2, %3, %4}], [lb], %6;\n\t}"                                      \
        :: "r"((uint32_t)(smem_addr)), "l"(map_ptr),                                    \
           "r"((int32_t)(cx)), "r"((int32_t)(cy)), "r"((int32_t)(cz)),                  \
           "r"((uint32_t)(mbar)), "h"((uint16_t)(cta_mask)) : "memory")

#define MBAR_ARRIVE_REMOTE(local_addr, target_rank) \
    asm volatile("{\n\t.reg .b32 ra;\n\t"                                               \
        "mapa.shared::cluster.u32 ra, %0, %1;\n\t"                                      \
        "mbarrier.arrive.shared::cluster.b64 _, [ra];\n\t}"                             \
        :: "r"((uint32_t)(local_addr)), "r"((uint32_t)(target_rank)) : "memory")

#define TCGEN05_ALLOC_CG2(smem_res, ncols) \
    asm volatile("tcgen05.alloc.cta_group::2.sync.aligned.shared::cta.b32 [%0], %1;"    \
        :: "r"((uint32_t)(smem_res)), "r"((uint32_t)(ncols)) : "memory")
#define TCGEN05_DEALLOC_CG2(tmem, ncols) \
    asm volatile("tcgen05.dealloc.cta_group::2.sync.aligned.b32 %0, %1;" :: "r"(tmem), "r"(ncols))
#define TCGEN05_RELINQ_CG2() \
    asm volatile("tcgen05.relinquish_alloc_permit.cta_group::2.sync.aligned;")
#define TCGEN05_COMMIT_MC_CG2(mbar, mask) \
    asm volatile("tcgen05.commit.cta_group::2.mbarrier::arrive::one.shared::cluster.multicast::cluster.b64 [%0], %1;" \
        :: "r"((uint32_t)(mbar)), "h"((uint16_t)(mask)) : "memory")
#define TCGEN05_FENCE_BEFORE() asm volatile("tcgen05.fence::before_thread_sync;" ::: "memory")
#define TCGEN05_FENCE_AFTER()  asm volatile("tcgen05.fence::after_thread_sync;" ::: "memory")
#define TCGEN05_WAIT_LD()      asm volatile("tcgen05.wait::ld.sync.aligned;" ::: "memory")

#define TCGEN05_LD_32X32B_X32(r, tmem_addr) \
    asm volatile("tcgen05.ld.sync.aligned.32x32b.x32.b32 "                              \
        "{%0, %1, %2, %3, %4, %5, %6, %7, "                                             \
        " %8, %9, %10, %11, %12, %13, %14, %15, "                                       \
        " %16, %17, %18, %19, %20, %21, %22, %23, "                                     \
        " %24, %25, %26, %27, %28, %29, %30, %31}, [%32];"                              \
        : "=r"((r)[0]),  "=r"((r)[1]),  "=r"((r)[2]),  "=r"((r)[3]),                    \
          "=r"((r)[4]),  "=r"((r)[5]),  "=r"((r)[6]),  "=r"((r)[7]),                    \
          "=r"((r)[8]),  "=r"((r)[9]),  "=r"((r)[10]), "=r"((r)[11]),                   \
          "=r"((r)[12]), "=r"((r)[13]), "=r"((r)[14]), "=r"((r)[15]),                   \
          "=r"((r)[16]), "=r"((r)[17]), "=r"((r)[18]), "=r"((r)[19]),                   \
          "=r"((r)[20]), "=r"((r)[21]), "=r"((r)[22]), "=r"((r)[23]),                   \
          "=r"((r)[24]), "=r"((r)[25]), "=r"((r)[26]), "=r"((r)[27]),                   \
          "=r"((r)[28]), "=r"((r)[29]), "=r"((r)[30]), "=r"((r)[31])                    \
        : "r"(tmem_addr))
#endif // GB300_TCGEN05

#define CLUSTER_SYNC() do {                                                             \
    asm volatile("barrier.cluster.arrive.aligned;" ::: "memory");                       \
    asm volatile("barrier.cluster.wait.aligned;" ::: "memory");                         \
} while (0)

__device__ __forceinline__ void mma_f16_ss_cg2(
    uint32_t d_tmem, uint64_t a_desc, uint64_t b_desc, uint32_t idesc, bool enable_d)
{
#if GB300_TCGEN05
    uint32_t en = enable_d ? 1u : 0u;
    asm volatile(
        "{\n\t.reg .pred p;\n\t"
        "setp.ne.u32 p, %5, 0;\n\t"
        "tcgen05.mma.cta_group::2.kind::f16 [%0], %1, %2, %3, "
        "{%4, %4, %4, %4, %4, %4, %4, %4}, p;\n\t}"
        :: "r"(d_tmem), "l"(a_desc), "l"(b_desc), "r"(idesc), "r"(0u), "r"(en)
        : "memory");
#endif
}

// tileid -> (m_base512, n_base) with GROUP_M supertile swizzle
__device__ __forceinline__ void tile_coords(int tileid, int& m512, int& nb) {
    const int group  = tileid / (GROUP_M * TILES_N);
    const int within = tileid % (GROUP_M * TILES_N);
    m512 = group * GROUP_M + (within % GROUP_M);
    nb   = within / GROUP_M;
}

// ======================= kernel 1: fused prep =======================
static constexpr int XB = (MM * KK / 4) / 256;   // 32768
static constexpr int WB = (NN * KK / 4) / 256;   // 65536

__global__ void __launch_bounds__(256) prep_kernel(
    const float* __restrict__ x, const float* __restrict__ w,
    const float* __restrict__ sc,
    __half* __restrict__ xh, __half* __restrict__ wh)
{
    int b = blockIdx.x;
    if (b < XB) {
        int i = b * 256 + threadIdx.x;
        float4 v = reinterpret_cast<const float4*>(x)[i];
        union { __half2 h[2]; uint2 u; } cv;
        cv.h[0] = __floats2half2_rn(v.x, v.y);
        cv.h[1] = __floats2half2_rn(v.z, v.w);
        reinterpret_cast<uint2*>(xh)[i] = cv.u;
    } else {
        int i = (b - XB) * 256 + threadIdx.x;
        int n  = i >> 10;
        int k4 = i & 1023;
        float s = __ldg(&sc[(n >> 7) * SCALE_KB + (k4 >> 5)]);
        float4 v = reinterpret_cast<const float4*>(w)[i];
        union { __half2 h[2]; uint2 u; } cv;
        cv.h[0] = __floats2half2_rn(v.x * s, v.y * s);
        cv.h[1] = __floats2half2_rn(v.z * s, v.w * s);
        reinterpret_cast<uint2*>(wh)[i] = cv.u;
    }
}

// ======================= kernel 2: PERSISTENT cluster-4 GEMM =======================
__global__ void __launch_bounds__(192, 1)
gemm_f16_kernel(const __grid_constant__ CUtensorMap tma_a,
                const __grid_constant__ CUtensorMap tma_b,
                const float* __restrict__ bias,
                float* __restrict__ out)
{
#if GB300_TCGEN05
    extern __shared__ char smem[];
    const uint32_t sb   = smem_u32(smem);
    const int tid       = threadIdx.x;
    const int wid       = tid >> 5;
    const int lid       = tid & 31;
    const uint32_t rank = ctarank();          // 0..3
    const int P   = (int)(rank >> 1);
    const int rp  = (int)(rank & 1);
    const int cid = blockIdx.x >> 2;          // cluster id [0, 32)
    const uint32_t pair_leader = rank & ~1u;

    // ---- init ----
    if (tid == 0) {
        #pragma unroll
        for (int s = 0; s < STAGES; s++) {
            MBAR_INIT(sb + SM_FULL  + s * 8, 1);   // leader's expect arrive only
            MBAR_INIT(sb + SM_EMPTY + s * 8, 2);   // both pair-leader commits
        }
        MBAR_INIT(sb + SM_DONE, 1);
        MBAR_INIT(sb + SM_ACCFREE + 0, 8);   // 4 warps x 2 CTAs per tile
        MBAR_INIT(sb + SM_ACCFREE + 8, 8);
    }
    if (wid == 5) TCGEN05_ALLOC_CG2(sb + SM_TMEM_PTR, 512);
    __syncthreads();
    uint32_t tmem_base;
    asm volatile("ld.shared.b32 %0, [%1];" : "=r"(tmem_base) : "r"(sb + SM_TMEM_PTR));
    CLUSTER_SYNC();

    // ---- producer: one thread per CTA ----
    if (tid == 128) {
        const uint16_t bmask = rp == 0 ? 0x5 : 0xA;   // {0,2} or {1,3}
        for (int j = 0; j < NROUNDS * KCHUNKS; ++j) {
            const int tile = j >> 6;
            const int kc   = j & (KCHUNKS - 1);
            int m512, nb;
            tile_coords(tile * NCLUST + cid, m512, nb);
            const int m_base_cta = m512 * 512 + P * 256 + rp * 128;
            const int n_base     = nb * 512;

            const int s = j & (STAGES - 1);
            const int r = j >> 2;
            if (r > 0) MBAR_WAIT_RELAXED(sb + SM_EMPTY + s * 8, (r - 1) & 1);
            const int kco = kc * BK;
            // merged full barrier: leader expects pair A (32K) + all B halves (64K)
            if (rp == 0) MBAR_EXPECT_TX(sb + SM_FULL + s * 8, FULL_TX);
            TMA_LOAD_3D_CG2(sb + SM_A + s * A_STAGE_BYTES, &tma_a,
                            kco, m_base_cta, 0, sb + SM_FULL + s * 8);
            // B: ranks 0,1 issue cg2+multicast loads; receivers' complete_tx
            // goes to their pair-leaders' full barriers (no software forward).
            if (rank < 2) {
                TMA_LOAD_3D_CG2_MC(sb + SM_B + s * B_STAGE_BYTES, &tma_b,
                                   kco, n_base + rp * 128, 0,
                                   sb + SM_FULL + s * 8, bmask);
                TMA_LOAD_3D_CG2_MC(sb + SM_B + s * B_STAGE_BYTES + 16384, &tma_b,
                                   kco, n_base + 256 + rp * 128, 0,
                                   sb + SM_FULL + s * 8, bmask);
            }
        }
    }

    // ---- MMA issuer: pair leaders only (single wait per chunk) ----
    if (tid == 160 && rp == 0) {
        for (int tile = 0; tile < NROUNDS; ++tile) {
            if (tile > 0) { MBAR_WAIT(sb + SM_ACCFREE + 0, (tile - 1) & 1); TCGEN05_FENCE_AFTER(); }
            for (int kc = 0; kc < KCHUNKS; ++kc) {
                const int j = tile * KCHUNKS + kc;
                const int s = j & (STAGES - 1);
                const int r = j >> 2;
                MBAR_WAIT(sb + SM_FULL + s * 8, r & 1);
                const uint64_t ad  = MAKE_SMEM_DESC(sb + SM_A + s * A_STAGE_BYTES);
                const uint64_t bd0 = MAKE_SMEM_DESC(sb + SM_B + s * B_STAGE_BYTES);
                #pragma unroll
                for (int ks = 0; ks < 4; ++ks)
                    mma_f16_ss_cg2(tmem_base, ad + ks * 2, bd0 + ks * 2,
                                   IDESC_F16, kc > 0 || ks > 0);
                if (kc == 0 && tile > 0) { MBAR_WAIT(sb + SM_ACCFREE + 8, (tile - 1) & 1); TCGEN05_FENCE_AFTER(); }
                const uint64_t bd1 = MAKE_SMEM_DESC(sb + SM_B + s * B_STAGE_BYTES + 16384);
                #pragma unroll
                for (int ks = 0; ks < 4; ++ks)
                    mma_f16_ss_cg2(tmem_base + 256, ad + ks * 2, bd1 + ks * 2,
                                   IDESC_F16, kc > 0 || ks > 0);
                TCGEN05_COMMIT_MC_CG2(sb + SM_EMPTY + s * 8, 0xF);
            }
            TCGEN05_COMMIT_MC_CG2(sb + SM_DONE, rank == 0 ? 0x3 : 0xC);
        }
    }

    // ---- epilogue: warps 0-3 on all CTAs ----
    if (wid < 4) {
        for (int tile = 0; tile < NROUNDS; ++tile) {
            MBAR_WAIT(sb + SM_DONE, tile & 1);
            TCGEN05_FENCE_AFTER();
            int m512, nb;
            tile_coords(tile * NCLUST + cid, m512, nb);
            const int m = m512 * 512 + P * 256 + rp * 128 + wid * 32 + lid;
            const int n_base = nb * 512;
            float* orow = out + (size_t)m * NN + n_base;
            #pragma unroll 1
            for (int cc = 0; cc < 16; ++cc) {
                uint32_t r[32];
                TCGEN05_LD_32X32B_X32(r, tmem_base + cc * 32);
                TCGEN05_WAIT_LD();
                if (cc == 7 || cc == 15) {    // half fully read -> release to next MMA
                    TCGEN05_FENCE_BEFORE();
                    if (lid == 0) MBAR_ARRIVE_REMOTE(sb + SM_ACCFREE + (cc == 7 ? 0 : 8), pair_leader);
                }
                const int n0 = cc * 32;
                #pragma unroll
                for (int q = 0; q < 8; ++q) {
                    float4 bv = __ldg(reinterpret_cast<const float4*>(bias + n_base + n0 + q * 4));
                    float4 o;
                    o.x = __uint_as_float(r[q * 4 + 0]) + bv.x;
                    o.y = __uint_as_float(r[q * 4 + 1]) + bv.y;
                    o.z = __uint_as_float(r[q * 4 + 2]) + bv.z;
                    o.w = __uint_as_float(r[q * 4 + 3]) + bv.w;
                    reinterpret_cast<float4*>(orow + n0)[q] = o;
                }
            }
        }
    }

    // ---- teardown ----
    __syncthreads();
    if (tid == 0) {
        #pragma unroll
        for (int s = 0; s < STAGES; s++) {
            MBAR_INVAL(sb + SM_FULL + s * 8);
            MBAR_INVAL(sb + SM_EMPTY + s * 8);
        }
        MBAR_INVAL(sb + SM_DONE);
        MBAR_INVAL(sb + SM_ACCFREE + 0);
        MBAR_INVAL(sb + SM_ACCFREE + 8);
    }
    __syncthreads();
    CLUSTER_SYNC();
    if (wid == 5) {
        TCGEN05_RELINQ_CG2();
        TCGEN05_DEALLOC_CG2(tmem_base, 512);
    }
    CLUSTER_SYNC();
#endif // GB300_TCGEN05
}

// ======================= host =======================
typedef CUresult (*PFN_tmapEncode)(
    CUtensorMap*, CUtensorMapDataType, cuuint32_t, void*,
    const cuuint64_t*, const cuuint64_t*, const cuuint32_t*, const cuuint32_t*,
    CUtensorMapInterleave, CUtensorMapSwizzle, CUtensorMapL2promotion, CUtensorMapFloatOOBfill);

static void make_kmajor_map(PFN_tmapEncode enc, CUtensorMap* m, void* base,
                            cuuint64_t d0, cuuint64_t d1)
{
    cuuint64_t dims[3]    = {d0, d1, 1};
    cuuint64_t strides[2] = {d0 * 2, d0 * d1 * 2};
    cuuint32_t box[3]     = {64, 128, 1};
    cuuint32_t es[3]      = {1, 1, 1};
    enc(m, CU_TENSOR_MAP_DATA_TYPE_FLOAT16, 3, base, dims, strides, box, es,
        CU_TENSOR_MAP_INTERLEAVE_NONE, CU_TENSOR_MAP_SWIZZLE_128B,
        CU_TENSOR_MAP_L2_PROMOTION_L2_128B, CU_TENSOR_MAP_FLOAT_OOB_FILL_NONE);
}

extern "C" void kernel_launch(void* const* d_in, const int* in_sizes, int n_in,
                              void* d_out, int out_size)
{
    const float* x    = (const float*)d_in[0];
    const float* w    = (const float*)d_in[1];
    const float* sc   = (const float*)d_in[2];
    const float* bias = (const float*)d_in[3];
    float* out        = (float*)d_out;

    void *xh = nullptr, *wh = nullptr;
    cudaGetSymbolAddress(&xh, g_x_h);
    cudaGetSymbolAddress(&wh, g_w_h);

    prep_kernel<<<XB + WB, 256>>>(x, w, sc, (__half*)xh, (__half*)wh);

    PFN_tmapEncode enc = nullptr;
    cudaDriverEntryPointQueryResult qr;
    cudaGetDriverEntryPoint("cuTensorMapEncodeTiled", (void**)&enc, cudaEnableDefault, &qr);
    if (!enc) return;

    CUtensorMap ta, tb;
    make_kmajor_map(enc, &ta, xh, (cuuint64_t)KK, (cuuint64_t)MM);
    make_kmajor_map(enc, &tb, wh, (cuuint64_t)KK, (cuuint64_t)NN);

    cudaFuncSetAttribute(gemm_f16_kernel,
                         cudaFuncAttributeMaxDynamicSharedMemorySize, SMEM_TOTAL);

    cudaLaunchConfig_t cfg = {};
    cfg.gridDim          = dim3(GRID, 1, 1);
    cfg.blockDim         = dim3(192, 1, 1);
    cfg.dynamicSmemBytes = SMEM_TOTAL;
    cfg.stream           = 0;
    cudaLaunchAttribute at[1];
    at[0].id = cudaLaunchAttributeClusterDimension;
    at[0].val.clusterDim.x = 4;
    at[0].val.clusterDim.y = 1;
    at[0].val.clusterDim.z = 1;
    cfg.attrs    = at;
    cfg.numAttrs = 1;
    cudaLaunchKernelEx(&cfg, gemm_f16_kernel, ta, tb, bias, out);
}

// round 13
// speedup vs baseline: 1.0226x; 1.0085x over previous
#include <cuda_runtime.h>
#include <cuda.h>
#include <cuda_fp16.h>
#include <cstdint>

// ---- arch gating: tcgen05 / cta_group::2 / TMA-multicast are only legal on
// arch-specific targets; the harness also builds a plain compute_103 PTX pass
// where ptxas rejects them.
#if !defined(__CUDA_ARCH__) || defined(__CUDA_ARCH_FEAT_SM103_ALL) || \
    defined(__CUDA_ARCH_FEAT_SM100_ALL) || defined(__CUDA_ARCH_FEAT_SM101_ALL) || \
    (defined(__CUDA_ARCH_FAMILY_SPECIFIC__) && (__CUDA_ARCH_FAMILY_SPECIFIC__ >= 1000))
#define GB300_TCGEN05 1
#else
#define GB300_TCGEN05 0
#endif

// ======================= problem constants =======================
static constexpr int MM = 8192;
static constexpr int KK = 4096;
static constexpr int NN = 16384;
static constexpr int SCALE_KB = KK / 128;

// ======================= gemm tiling =======================
// 4-CTA cluster = 2 cg2 pairs sharing one 512-N range (B multicast {0,2},{1,3}).
// Cluster tile: 512M x 512N. PERSISTENT: 32 clusters x 16 tiles each.
static constexpr int BK         = 64;
static constexpr int STAGES     = 4;
static constexpr int KCHUNKS    = KK / BK;          // 64
static constexpr int TILES_N    = NN / 512;         // 32
static constexpr int TILES_TOT  = (MM / 512) * TILES_N;  // 512
static constexpr int NCLUST     = 32;
static constexpr int GRID       = NCLUST * 4;       // 128 CTAs
static constexpr int NROUNDS    = TILES_TOT / NCLUST;    // 16
static constexpr int GROUP_M    = 8;

// smem layout
static constexpr int SM_TMEM_PTR   = 0;
static constexpr int SM_FULL       = 16;    // 4 x 8B (merged A+B, pair-leader only)
static constexpr int SM_EMPTY      = 48;    // 4 x 8B
static constexpr int SM_DONE       = 80;    // 8B
static constexpr int SM_ACCFREE    = 88;    // 2 x 8B (per 256-col half)
static constexpr int A_STAGE_BYTES = 128 * 128;          // 16 KB per CTA
static constexpr int B_STAGE_BYTES = 2 * 128 * 128;      // 32 KB per CTA
static constexpr int SM_A          = 1024;
static constexpr int SM_B          = SM_A + STAGES * A_STAGE_BYTES;
static constexpr int SMEM_TOTAL    = SM_B + STAGES * B_STAGE_BYTES;   // 197632
static constexpr unsigned FULL_TX  = 6u * 128u * 128u;   // pair A + 4 B halves

// idesc kind::f16, f16 in, fp32 acc, M=256 (cg2), N=256
static constexpr uint32_t IDESC_F16 =
    (1u << 4) | ((256u / 8) << 17) | ((256u / 16) << 24);

static constexpr uint64_t SMEM_DESC_BASE_SW128 =
    (uint64_t(2) << 61) | (uint64_t(1) << 46) | (uint64_t(64) << 32) | (uint64_t(1) << 16);
#define MAKE_SMEM_DESC(base_addr) (SMEM_DESC_BASE_SW128 | ((uint64_t)((base_addr) >> 4) & 0x3FFF))

// ======================= device scratch =======================
__device__ __align__(1024) __half g_x_h[(size_t)MM * KK];   // 64 MB
__device__ __align__(1024) __half g_w_h[(size_t)NN * KK];   // 128 MB

// ======================= PTX helpers =======================
__device__ __forceinline__ uint32_t smem_u32(const void* p) {
    uint32_t a;
    asm("{ .reg .u64 t; cvta.to.shared.u64 t, %1; cvt.u32.u64 %0, t; }" : "=r"(a) : "l"(p));
    return a;
}
__device__ __forceinline__ uint32_t ctarank() {
    uint32_t r; asm("mov.u32 %0, %%cluster_ctarank;" : "=r"(r)); return r;
}

#define MBAR_INIT(addr, cnt) \
    asm volatile("mbarrier.init.shared.b64 [%0], %1;" :: "r"(addr), "r"(cnt) : "memory")
#define MBAR_INVAL(addr) \
    asm volatile("mbarrier.inval.shared.b64 [%0];" :: "r"(addr) : "memory")
#define MBAR_EXPECT_TX(addr, bytes) \
    asm volatile("mbarrier.arrive.expect_tx.shared.b64 _, [%0], %1;" :: "r"(addr), "r"(bytes) : "memory")

#define MBAR_WAIT(addr, parity) do {                                                    \
    uint32_t _m = (uint32_t)(addr); uint32_t _p = (uint32_t)(parity); uint32_t _d;      \
    asm volatile("{\n\t.reg .pred p;\n\t"                                               \
        "mbarrier.try_wait.parity.acquire.cta.shared::cta.b64 p, [%1], %2;\n\t"         \
        "selp.b32 %0, 1, 0, p;\n\t}" : "=r"(_d) : "r"(_m), "r"(_p) : "memory");         \
    if (!_d) {                                                                          \
        asm volatile("{\n\t.reg .pred P1;\n\t"                                          \
            "WAIT_LOOP_%=:\n\t"                                                         \
            "mbarrier.try_wait.parity.acquire.cta.shared::cta.b64 P1, [%0], %1, 0x989680;\n\t" \
            "@P1 bra.uni WAIT_DONE_%=;\n\t"                                             \
            "bra.uni WAIT_LOOP_%=;\n\t"                                                 \
            "WAIT_DONE_%=:\n\t}" :: "r"(_m), "r"(_p) : "memory");                       \
    }                                                                                   \
} while (0)

#define MBAR_WAIT_RELAXED(addr, parity) do {                                            \
    uint32_t _m = (uint32_t)(addr); uint32_t _p = (uint32_t)(parity); uint32_t _d;      \
    asm volatile("{\n\t.reg .pred p;\n\t"                                               \
        "mbarrier.try_wait.parity.relaxed.cta.shared::cta.b64 p, [%1], %2, 0x989680;\n\t" \
        "selp.b32 %0, 1, 0, p;\n\t}" : "=r"(_d) : "r"(_m), "r"(_p) : "memory");         \
    if (!_d) {                                                                          \
        asm volatile("{\n\t.reg .pred P1;\n\t"                                          \
            "WAIT_LOOP_%=:\n\t"                                                         \
            "mbarrier.try_wait.parity.relaxed.cta.shared::cta.b64 P1, [%0], %1, 0x989680;\n\t" \
            "@P1 bra.uni WAIT_DONE_%=;\n\t"                                             \
            "bra.uni WAIT_LOOP_%=;\n\t"                                                 \
            "WAIT_DONE_%=:\n\t}" :: "r"(_m), "r"(_p) : "memory");                       \
    }                                                                                   \
} while (0)

#if GB300_TCGEN05
// cg2 TMA load: complete_tx targets the pair-leader's barrier (bit 24 cleared).
#define TMA_LOAD_3D_CG2(smem_addr, map_ptr, cx, cy, cz, mbar) \
    asm volatile("{\n\t.reg .b32 lb;\n\t"                                               \
        "and.b32 lb, %5, 0xFEFFFFFF;\n\t"                                               \
        "cp.async.bulk.tensor.3d.cta_group::2.shared::cluster.global"                   \
        ".tile.mbarrier::complete_tx::bytes [%0], [%1, {%2, %3, %4}], [lb];\n\t}"       \
        :: "r"((uint32_t)(smem_addr)), "l"(map_ptr),                                    \
           "r"((int32_t)(cx)), "r"((int32_t)(cy)), "r"((int32_t)(cz)),                  \
           "r"((uint32_t)(mbar)) : "memory")

// cg2 + multicast: data to every CTA in cta_mask; each receiver's complete_tx
// is credited to its PAIR-LEADER's barrier.
#define TMA_LOAD_3D_CG2_MC(smem_addr, map_ptr, cx, cy, cz, mbar, cta_mask) \
    asm volatile("{\n\t.reg .b32 lb;\n\t"                                               \
        "and.b32 lb, %5, 0xFEFFFFFF;\n\t"                                               \
        "cp.async.bulk.tensor.3d.cta_group::2.shared::cluster.global"                   \
        ".tile.mbarrier::complete_tx::bytes.multicast::cluster "                        \
        "[%0], [%1, {%2, %3, %4}], [lb], %6;\n\t}"                                      \
        :: "r"((uint32_t)(smem_addr)), "l"(map_ptr),                                    \
           "r"((int32_t)(cx)), "r"((int32_t)(cy)), "r"((int32_t)(cz)),                  \
           "r"((uint32_t)(mbar)), "h"((uint16_t)(cta_mask)) : "memory")

#define MBAR_ARRIVE_REMOTE(local_addr, target_rank) \
    asm volatile("{\n\t.reg .b32 ra;\n\t"                                               \
        "mapa.shared::cluster.u32 ra, %0, %1;\n\t"                                      \
        "mbarrier.arrive.shared::cluster.b64 _, [ra];\n\t}"                             \
        :: "r"((uint32_t)(local_addr)), "r"((uint32_t)(target_rank)) : "memory")

#define TCGEN05_ALLOC_CG2(smem_res, ncols) \
    asm volatile("tcgen05.alloc.cta_group::2.sync.aligned.shared::cta.b32 [%0], %1;"    \
        :: "r"((uint32_t)(smem_res)), "r"((uint32_t)(ncols)) : "memory")
#define TCGEN05_DEALLOC_CG2(tmem, ncols) \
    asm volatile("tcgen05.dealloc.cta_group::2.sync.aligned.b32 %0, %1;" :: "r"(tmem), "r"(ncols))
#define TCGEN05_RELINQ_CG2() \
    asm volatile("tcgen05.relinquish_alloc_permit.cta_group::2.sync.aligned;")
#define TCGEN05_COMMIT_MC_CG2(mbar, mask) \
    asm volatile("tcgen05.commit.cta_group::2.mbarrier::arrive::one.shared::cluster.multicast::cluster.b64 [%0], %1;" \
        :: "r"((uint32_t)(mbar)), "h"((uint16_t)(mask)) : "memory")
#define TCGEN05_FENCE_BEFORE() asm volatile("tcgen05.fence::before_thread_sync;" ::: "memory")
#define TCGEN05_FENCE_AFTER()  asm volatile("tcgen05.fence::after_thread_sync;" ::: "memory")
#define TCGEN05_WAIT_LD()      asm volatile("tcgen05.wait::ld.sync.aligned;" ::: "memory")

#define TCGEN05_LD_32X32B_X32(r, tmem_addr) \
    asm volatile("tcgen05.ld.sync.aligned.32x32b.x32.b32 "                              \
        "{%0, %1, %2, %3, %4, %5, %6, %7, "                                             \
        " %8, %9, %10, %11, %12, %13, %14, %15, "                                       \
        " %16, %17, %18, %19, %20, %21, %22, %23, "                                     \
        " %24, %25, %26, %27, %28, %29, %30, %31}, [%32];"                              \
        : "=r"((r)[0]),  "=r"((r)[1]),  "=r"((r)[2]),  "=r"((r)[3]),                    \
          "=r"((r)[4]),  "=r"((r)[5]),  "=r"((r)[6]),  "=r"((r)[7]),                    \
          "=r"((r)[8]),  "=r"((r)[9]),  "=r"((r)[10]), "=r"((r)[11]),                   \
          "=r"((r)[12]), "=r"((r)[13]), "=r"((r)[14]), "=r"((r)[15]),                   \
          "=r"((r)[16]), "=r"((r)[17]), "=r"((r)[18]), "=r"((r)[19]),                   \
          "=r"((r)[20]), "=r"((r)[21]), "=r"((r)[22]), "=r"((r)[23]),                   \
          "=r"((r)[24]), "=r"((r)[25]), "=r"((r)[26]), "=r"((r)[27]),                   \
          "=r"((r)[28]), "=r"((r)[29]), "=r"((r)[30]), "=r"((r)[31])                    \
        : "r"(tmem_addr))
#endif // GB300_TCGEN05

#define CLUSTER_SYNC() do {                                                             \
    asm volatile("barrier.cluster.arrive.aligned;" ::: "memory");                       \
    asm volatile("barrier.cluster.wait.aligned;" ::: "memory");                         \
} while (0)

__device__ __forceinline__ void mma_f16_ss_cg2(
    uint32_t d_tmem, uint64_t a_desc, uint64_t b_desc, uint32_t idesc, bool enable_d)
{
#if GB300_TCGEN05
    uint32_t en = enable_d ? 1u : 0u;
    asm volatile(
        "{\n\t.reg .pred p;\n\t"
        "setp.ne.u32 p, %5, 0;\n\t"
        "tcgen05.mma.cta_group::2.kind::f16 [%0], %1, %2, %3, "
        "{%4, %4, %4, %4, %4, %4, %4, %4}, p;\n\t}"
        :: "r"(d_tmem), "l"(a_desc), "l"(b_desc), "r"(idesc), "r"(0u), "r"(en)
        : "memory");
#endif
}

// tileid -> (m_base512, n_base) with GROUP_M supertile swizzle
__device__ __forceinline__ void tile_coords(int tileid, int& m512, int& nb) {
    const int group  = tileid / (GROUP_M * TILES_N);
    const int within = tileid % (GROUP_M * TILES_N);
    m512 = group * GROUP_M + (within % GROUP_M);
    nb   = within / GROUP_M;
}

// ======================= kernel 1: fused prep =======================
static constexpr int XB = (MM * KK / 4) / 256;   // 32768
static constexpr int WB = (NN * KK / 4) / 256;   // 65536

__global__ void __launch_bounds__(256) prep_kernel(
    const float* __restrict__ x, const float* __restrict__ w,
    const float* __restrict__ sc,
    __half* __restrict__ xh, __half* __restrict__ wh)
{
    int b = blockIdx.x;
    if (b < XB) {
        int i = b * 256 + threadIdx.x;
        float4 v = reinterpret_cast<const float4*>(x)[i];
        union { __half2 h[2]; uint2 u; } cv;
        cv.h[0] = __floats2half2_rn(v.x, v.y);
        cv.h[1] = __floats2half2_rn(v.z, v.w);
        reinterpret_cast<uint2*>(xh)[i] = cv.u;
    } else {
        int i = (b - XB) * 256 + threadIdx.x;
        int n  = i >> 10;
        int k4 = i & 1023;
        float s = __ldg(&sc[(n >> 7) * SCALE_KB + (k4 >> 5)]);
        float4 v = reinterpret_cast<const float4*>(w)[i];
        union { __half2 h[2]; uint2 u; } cv;
        cv.h[0] = __floats2half2_rn(v.x * s, v.y * s);
        cv.h[1] = __floats2half2_rn(v.z * s, v.w * s);
        reinterpret_cast<uint2*>(wh)[i] = cv.u;
    }
}

// ======================= kernel 2: PERSISTENT cluster-4 GEMM =======================
__global__ void __launch_bounds__(192, 1)
gemm_f16_kernel(const __grid_constant__ CUtensorMap tma_a,
                const __grid_constant__ CUtensorMap tma_b,
                const float* __restrict__ bias,
                float* __restrict__ out)
{
#if GB300_TCGEN05
    extern __shared__ char smem[];
    const uint32_t sb   = smem_u32(smem);
    const int tid       = threadIdx.x;
    const int wid       = tid >> 5;
    const int lid       = tid & 31;
    const uint32_t rank = ctarank();          // 0..3
    const int P   = (int)(rank >> 1);
    const int rp  = (int)(rank & 1);
    const int cid = blockIdx.x >> 2;          // cluster id [0, 32)
    const uint32_t pair_leader = rank & ~1u;

    // ---- init ----
    if (tid == 0) {
        #pragma unroll
        for (int s = 0; s < STAGES; s++) {
            MBAR_INIT(sb + SM_FULL  + s * 8, 1);
            MBAR_INIT(sb + SM_EMPTY + s * 8, 2);
        }
        MBAR_INIT(sb + SM_DONE, 1);
        MBAR_INIT(sb + SM_ACCFREE + 0, 8);   // 4 warps x 2 CTAs per tile
        MBAR_INIT(sb + SM_ACCFREE + 8, 8);
    }
    if (wid == 5) TCGEN05_ALLOC_CG2(sb + SM_TMEM_PTR, 512);
    __syncthreads();
    uint32_t tmem_base;
    asm volatile("ld.shared.b32 %0, [%1];" : "=r"(tmem_base) : "r"(sb + SM_TMEM_PTR));
    CLUSTER_SYNC();

    // ---- producer: one thread per CTA ----
    if (tid == 128) {
        const uint16_t bmask = rp == 0 ? 0x5 : 0xA;   // {0,2} or {1,3}
        for (int j = 0; j < NROUNDS * KCHUNKS; ++j) {
            const int tile = j >> 6;
            const int kc   = j & (KCHUNKS - 1);
            int m512, nb;
            tile_coords(tile * NCLUST + cid, m512, nb);
            const int m_base_cta = m512 * 512 + P * 256 + rp * 128;
            const int n_base     = nb * 512;

            const int s = j & (STAGES - 1);
            const int r = j >> 2;
            if (r > 0) MBAR_WAIT_RELAXED(sb + SM_EMPTY + s * 8, (r - 1) & 1);
            const int kco = kc * BK;
            if (rp == 0) MBAR_EXPECT_TX(sb + SM_FULL + s * 8, FULL_TX);
            TMA_LOAD_3D_CG2(sb + SM_A + s * A_STAGE_BYTES, &tma_a,
                            kco, m_base_cta, 0, sb + SM_FULL + s * 8);
            if (rank < 2) {
                TMA_LOAD_3D_CG2_MC(sb + SM_B + s * B_STAGE_BYTES, &tma_b,
                                   kco, n_base + rp * 128, 0,
                                   sb + SM_FULL + s * 8, bmask);
                TMA_LOAD_3D_CG2_MC(sb + SM_B + s * B_STAGE_BYTES + 16384, &tma_b,
                                   kco, n_base + 256 + rp * 128, 0,
                                   sb + SM_FULL + s * 8, bmask);
            }
        }
    }

    // ---- MMA issuer: pair leaders only. Dispatches INTERLEAVE the two
    //      N-halves so consecutive dispatches hit different accumulators
    //      (hides same-D accumulator RAW turnaround). ----
    if (tid == 160 && rp == 0) {
        for (int tile = 0; tile < NROUNDS; ++tile) {
            if (tile > 0) {
                MBAR_WAIT(sb + SM_ACCFREE + 0, (tile - 1) & 1);
                MBAR_WAIT(sb + SM_ACCFREE + 8, (tile - 1) & 1);
                TCGEN05_FENCE_AFTER();
            }
            for (int kc = 0; kc < KCHUNKS; ++kc) {
                const int j = tile * KCHUNKS + kc;
                const int s = j & (STAGES - 1);
                const int r = j >> 2;
                MBAR_WAIT(sb + SM_FULL + s * 8, r & 1);
                uint64_t ad  = MAKE_SMEM_DESC(sb + SM_A + s * A_STAGE_BYTES);
                uint64_t bd0 = MAKE_SMEM_DESC(sb + SM_B + s * B_STAGE_BYTES);
                uint64_t bd1 = MAKE_SMEM_DESC(sb + SM_B + s * B_STAGE_BYTES + 16384);
                const bool acc0 = kc > 0;
                #pragma unroll 4
                for (int ks = 0; ks < 4; ++ks) {
                    mma_f16_ss_cg2(tmem_base,       ad, bd0, IDESC_F16, acc0 || ks > 0);
                    mma_f16_ss_cg2(tmem_base + 256, ad, bd1, IDESC_F16, acc0 || ks > 0);
                    ad += 2; bd0 += 2; bd1 += 2;
                }
                TCGEN05_COMMIT_MC_CG2(sb + SM_EMPTY + s * 8, 0xF);
            }
            TCGEN05_COMMIT_MC_CG2(sb + SM_DONE, rank == 0 ? 0x3 : 0xC);
        }
    }

    // ---- epilogue: warps 0-3 on all CTAs ----
    if (wid < 4) {
        for (int tile = 0; tile < NROUNDS; ++tile) {
            MBAR_WAIT(sb + SM_DONE, tile & 1);
            TCGEN05_FENCE_AFTER();
            int m512, nb;
            tile_coords(tile * NCLUST + cid, m512, nb);
            const int m = m512 * 512 + P * 256 + rp * 128 + wid * 32 + lid;
            const int n_base = nb * 512;
            float* orow = out + (size_t)m * NN + n_base;
            #pragma unroll 1
            for (int cc = 0; cc < 16; ++cc) {
                uint32_t r[32];
                TCGEN05_LD_32X32B_X32(r, tmem_base + cc * 32);
                TCGEN05_WAIT_LD();
                if (cc == 7 || cc == 15) {    // half fully read -> release to next MMA
                    TCGEN05_FENCE_BEFORE();
                    if (lid == 0) MBAR_ARRIVE_REMOTE(sb + SM_ACCFREE + (cc == 7 ? 0 : 8), pair_leader);
                }
                const int n0 = cc * 32;
                #pragma unroll
                for (int q = 0; q < 8; ++q) {
                    float4 bv = __ldg(reinterpret_cast<const float4*>(bias + n_base + n0 + q * 4));
                    float4 o;
                    o.x = __uint_as_float(r[q * 4 + 0]) + bv.x;
                    o.y = __uint_as_float(r[q * 4 + 1]) + bv.y;
                    o.z = __uint_as_float(r[q * 4 + 2]) + bv.z;
                    o.w = __uint_as_float(r[q * 4 + 3]) + bv.w;
                    reinterpret_cast<float4*>(orow + n0)[q] = o;
                }
            }
        }
    }

    // ---- teardown ----
    __syncthreads();
    if (tid == 0) {
        #pragma unroll
        for (int s = 0; s < STAGES; s++) {
            MBAR_INVAL(sb + SM_FULL + s * 8);
            MBAR_INVAL(sb + SM_EMPTY + s * 8);
        }
        MBAR_INVAL(sb + SM_DONE);
        MBAR_INVAL(sb + SM_ACCFREE + 0);
        MBAR_INVAL(sb + SM_ACCFREE + 8);
    }
    __syncthreads();
    CLUSTER_SYNC();
    if (wid == 5) {
        TCGEN05_RELINQ_CG2();
        TCGEN05_DEALLOC_CG2(tmem_base, 512);
    }
    CLUSTER_SYNC();
#endif // GB300_TCGEN05
}

// ======================= host =======================
typedef CUresult (*PFN_tmapEncode)(
    CUtensorMap*, CUtensorMapDataType, cuuint32_t, void*,
    const cuuint64_t*, const cuuint64_t*, const cuuint32_t*, const cuuint32_t*,
    CUtensorMapInterleave, CUtensorMapSwizzle, CUtensorMapL2promotion, CUtensorMapFloatOOBfill);

static void make_kmajor_map(PFN_tmapEncode enc, CUtensorMap* m, void* base,
                            cuuint64_t d0, cuuint64_t d1)
{
    cuuint64_t dims[3]    = {d0, d1, 1};
    cuuint64_t strides[2] = {d0 * 2, d0 * d1 * 2};
    cuuint32_t box[3]     = {64, 128, 1};
    cuuint32_t es[3]      = {1, 1, 1};
    enc(m, CU_TENSOR_MAP_DATA_TYPE_FLOAT16, 3, base, dims, strides, box, es,
        CU_TENSOR_MAP_INTERLEAVE_NONE, CU_TENSOR_MAP_SWIZZLE_128B,
        CU_TENSOR_MAP_L2_PROMOTION_L2_128B, CU_TENSOR_MAP_FLOAT_OOB_FILL_NONE);
}

extern "C" void kernel_launch(void* const* d_in, const int* in_sizes, int n_in,
                              void* d_out, int out_size)
{
    const float* x    = (const float*)d_in[0];
    const float* w    = (const float*)d_in[1];
    const float* sc   = (const float*)d_in[2];
    const float* bias = (const float*)d_in[3];
    float* out        = (float*)d_out;

    void *xh = nullptr, *wh = nullptr;
    cudaGetSymbolAddress(&xh, g_x_h);
    cudaGetSymbolAddress(&wh, g_w_h);

    prep_kernel<<<XB + WB, 256>>>(x, w, sc, (__half*)xh, (__half*)wh);

    PFN_tmapEncode enc = nullptr;
    cudaDriverEntryPointQueryResult qr;
    cudaGetDriverEntryPoint("cuTensorMapEncodeTiled", (void**)&enc, cudaEnableDefault, &qr);
    if (!enc) return;

    CUtensorMap ta, tb;
    make_kmajor_map(enc, &ta, xh, (cuuint64_t)KK, (cuuint64_t)MM);
    make_kmajor_map(enc, &tb, wh, (cuuint64_t)KK, (cuuint64_t)NN);

    cudaFuncSetAttribute(gemm_f16_kernel,
                         cudaFuncAttributeMaxDynamicSharedMemorySize, SMEM_TOTAL);

    cudaLaunchConfig_t cfg = {};
    cfg.gridDim          = dim3(GRID, 1, 1);
    cfg.blockDim         = dim3(192, 1, 1);
    cfg.dynamicSmemBytes = SMEM_TOTAL;
    cfg.stream           = 0;
    cudaLaunchAttribute at[1];
    at[0].id = cudaLaunchAttributeClusterDimension;
    at[0].val.clusterDim.x = 4;
    at[0].val.clusterDim.y = 1;
    at[0].val.clusterDim.z = 1;
    cfg.attrs    = at;
    cfg.numAttrs = 1;
    cudaLaunchKernelEx(&cfg, gemm_f16_kernel, ta, tb, bias, out);
}